// round 2
// baseline (speedup 1.0000x reference)
#include <cuda_runtime.h>

// CovarianceLayer: x [64, 4, 8192, 16] fp32 -> cov [64, 4, 16, 16] fp32
// Two-stage: (1) 1024 CTAs, each covers one (b,c) x T/4 chunk, accumulates
// upper-triangle sum-of-products (136) + column sums (16) in registers with a
// software-pipelined 1-row-ahead prefetch; writes partials to device scratch.
// (2) 256 CTAs combine 4 partials and finalize cov = (S - s_m s_n/T)/(T-1).

#define T_DIM    8192
#define M_DIM    16
#define NTHREADS 256
#define NPAIRS   136             // 16*17/2
#define NACC     152             // 136 products + 16 sums
#define SPLIT    4
#define ROWS_PER_CTA (T_DIM / SPLIT)        // 2048
#define K_ITERS  (ROWS_PER_CTA / NTHREADS)  // 8

__device__ float g_partial[256 * SPLIT * NACC];   // 623 KB scratch

__device__ __forceinline__ int tri_idx(int m, int n) {   // m <= n
    return m * (31 - m) / 2 + n;
}

__device__ __forceinline__ void load_row(float4 r[4], const float4* __restrict__ p) {
    r[0] = p[0]; r[1] = p[1]; r[2] = p[2]; r[3] = p[3];
}

__device__ __forceinline__ void accum_row(float acc[NACC], const float4 r[4]) {
    float v[M_DIM] = { r[0].x, r[0].y, r[0].z, r[0].w,
                       r[1].x, r[1].y, r[1].z, r[1].w,
                       r[2].x, r[2].y, r[2].z, r[2].w,
                       r[3].x, r[3].y, r[3].z, r[3].w };
    #pragma unroll
    for (int m = 0; m < M_DIM; m++) {
        acc[NPAIRS + m] += v[m];
        #pragma unroll
        for (int n = m; n < M_DIM; n++)
            acc[tri_idx(m, n)] = fmaf(v[m], v[n], acc[tri_idx(m, n)]);
    }
}

__global__ void __launch_bounds__(NTHREADS, 1)
cov_partial_kernel(const float* __restrict__ x)
{
    const int cta   = blockIdx.x;          // 0..1023
    const int bc    = cta >> 2;            // (b,c) pair
    const int split = cta & 3;             // T chunk
    const int tid   = threadIdx.x;

    // Base pointer: row (split*ROWS_PER_CTA + tid) of this (b,c) slab.
    const float4* __restrict__ rp = reinterpret_cast<const float4*>(
        x + (size_t)bc * T_DIM * M_DIM) + (size_t)(split * ROWS_PER_CTA + tid) * 4;
    const int stride = NTHREADS * 4;       // float4 units per k-step

    float acc[NACC];
    #pragma unroll
    for (int i = 0; i < NACC; i++) acc[i] = 0.0f;

    // Software-pipelined: while accumulating row A, row B's loads are in flight.
    float4 a[4];
    load_row(a, rp);
    #pragma unroll 1
    for (int k = 0; k < K_ITERS; k += 2) {
        float4 b[4];
        load_row(b, rp + (size_t)(k + 1) * stride);
        accum_row(acc, a);
        if (k + 2 < K_ITERS)
            load_row(a, rp + (size_t)(k + 2) * stride);
        accum_row(acc, b);
    }

    // ---- Reduce 152 accumulators across the 256 threads ----
    #pragma unroll 1
    for (int i = 0; i < NACC; i++) {
        float v = acc[i];
        #pragma unroll
        for (int o = 16; o > 0; o >>= 1)
            v += __shfl_xor_sync(0xFFFFFFFFu, v, o);
        acc[i] = v;
    }

    __shared__ float red[NTHREADS / 32][NACC];
    const int wid = tid >> 5;
    const int lid = tid & 31;
    if (lid == 0) {
        #pragma unroll 1
        for (int i = 0; i < NACC; i++) red[wid][i] = acc[i];
    }
    __syncthreads();

    if (tid < NACC) {
        float v = 0.0f;
        #pragma unroll
        for (int w = 0; w < NTHREADS / 32; w++) v += red[w][tid];
        g_partial[cta * NACC + tid] = v;
    }
}

__global__ void __launch_bounds__(NTHREADS)
cov_finalize_kernel(float* __restrict__ out)
{
    const int bc  = blockIdx.x;            // 0..255
    const int tid = threadIdx.x;

    __shared__ float tot[NACC];
    if (tid < NACC) {
        const float* p = &g_partial[bc * SPLIT * NACC + tid];
        float v = 0.0f;
        #pragma unroll
        for (int s = 0; s < SPLIT; s++) v += p[s * NACC];
        tot[tid] = v;
    }
    __syncthreads();

    const int m  = tid >> 4;
    const int n  = tid & 15;
    const int mm = (m < n) ? m : n;
    const int nn = (m < n) ? n : m;
    const float S  = tot[tri_idx(mm, nn)];
    const float sm = tot[NPAIRS + m];
    const float sn = tot[NPAIRS + n];
    const float inv_T  = 1.0f / (float)T_DIM;
    const float inv_T1 = 1.0f / (float)(T_DIM - 1);
    out[(size_t)bc * 256 + tid] = (S - sm * sn * inv_T) * inv_T1;
}

extern "C" void kernel_launch(void* const* d_in, const int* in_sizes, int n_in,
                              void* d_out, int out_size)
{
    const float* x = (const float*)d_in[0];
    float* out = (float*)d_out;
    cov_partial_kernel<<<256 * SPLIT, NTHREADS>>>(x);
    cov_finalize_kernel<<<256, NTHREADS>>>(out);
}

// round 3
// speedup vs baseline: 3.1702x; 3.1702x over previous
#include <cuda_runtime.h>

// CovarianceLayer: x [64, 4, 8192, 16] fp32 -> cov [64, 4, 16, 16] fp32
// One CTA per (b,c). Double-buffered smem pipeline:
//   - coalesced LDG of a 256-row x 16-col tile (16KB) into registers
//   - STS into a TRANSPOSED smem tile (col-major, pitch 257 -> conflict-free LDS)
//   - each thread computes the 136-pair upper triangle + 16 sums for one row/tile
//     in registers (152 accumulators), fully unrolled static indexing.
// Epilogue: warp shfl reduce + smem cross-warp reduce + inline finalize.

#define T_DIM    8192
#define M_DIM    16
#define NTHREADS 256
#define NPAIRS   136            // 16*17/2
#define NACC     152            // 136 products + 16 sums
#define TILE_ROWS 256
#define NTILES   (T_DIM / TILE_ROWS)   // 32
#define PITCH    257            // words per transposed column (256 + 1 pad)

__device__ __forceinline__ int tri_idx(int m, int n) {   // m <= n
    return m * (31 - m) / 2 + n;
}

__global__ void __launch_bounds__(NTHREADS, 1)
cov_kernel(const float* __restrict__ x, float* __restrict__ out)
{
    __shared__ float smem[2][M_DIM * PITCH];     // 2 x 16.4 KB transposed tiles
    __shared__ float red[NTHREADS / 32][NACC];   // cross-warp reduce

    const int bc  = blockIdx.x;            // (b,c) pair
    const int tid = threadIdx.x;
    const int q   = tid & 3;               // quarter (float4 index) this thread loads
    const int r0  = tid >> 2;              // base row (of 64-row group) this thread loads

    const float4* __restrict__ xp =
        reinterpret_cast<const float4*>(x + (size_t)bc * T_DIM * M_DIM);
    // float4 index f within tile: row = f>>2, quarter = f&3. Tile k base = 1024*k.

    float acc[NACC];
    #pragma unroll
    for (int i = 0; i < NACC; i++) acc[i] = 0.0f;

    float4 pf[4];

    // ---- prologue: load tile 0, stage it, prefetch tile 1 ----
    #pragma unroll
    for (int j = 0; j < 4; j++) pf[j] = xp[tid + 256 * j];

    #pragma unroll
    for (int j = 0; j < 4; j++) {
        const int r = r0 + 64 * j;
        smem[0][(4 * q + 0) * PITCH + r] = pf[j].x;
        smem[0][(4 * q + 1) * PITCH + r] = pf[j].y;
        smem[0][(4 * q + 2) * PITCH + r] = pf[j].z;
        smem[0][(4 * q + 3) * PITCH + r] = pf[j].w;
    }

    #pragma unroll
    for (int j = 0; j < 4; j++) pf[j] = xp[1024 + tid + 256 * j];

    __syncthreads();

    // ---- main loop over 32 tiles ----
    int cur = 0;
    #pragma unroll 1
    for (int k = 0; k < NTILES; k++) {
        // stage prefetched tile k+1 into the other buffer
        if (k + 1 < NTILES) {
            #pragma unroll
            for (int j = 0; j < 4; j++) {
                const int r = r0 + 64 * j;
                smem[cur ^ 1][(4 * q + 0) * PITCH + r] = pf[j].x;
                smem[cur ^ 1][(4 * q + 1) * PITCH + r] = pf[j].y;
                smem[cur ^ 1][(4 * q + 2) * PITCH + r] = pf[j].z;
                smem[cur ^ 1][(4 * q + 3) * PITCH + r] = pf[j].w;
            }
        }
        // issue loads for tile k+2 (land during compute + sync)
        if (k + 2 < NTILES) {
            #pragma unroll
            for (int j = 0; j < 4; j++)
                pf[j] = xp[1024 * (k + 2) + tid + 256 * j];
        }

        // compute row `tid` of tile k from transposed smem (conflict-free LDS)
        float v[M_DIM];
        #pragma unroll
        for (int i = 0; i < M_DIM; i++) v[i] = smem[cur][i * PITCH + tid];

        #pragma unroll
        for (int m = 0; m < M_DIM; m++) {
            acc[NPAIRS + m] += v[m];
            #pragma unroll
            for (int n = m; n < M_DIM; n++)
                acc[tri_idx(m, n)] = fmaf(v[m], v[n], acc[tri_idx(m, n)]);
        }

        __syncthreads();
        cur ^= 1;
    }

    // ---- reduce 152 accumulators across 256 threads ----
    #pragma unroll 1
    for (int i = 0; i < NACC; i++) {
        float s = acc[i];
        #pragma unroll
        for (int o = 16; o > 0; o >>= 1)
            s += __shfl_xor_sync(0xFFFFFFFFu, s, o);
        acc[i] = s;
    }

    const int wid = tid >> 5;
    const int lid = tid & 31;
    if (lid == 0) {
        #pragma unroll 1
        for (int i = 0; i < NACC; i++) red[wid][i] = acc[i];
    }
    __syncthreads();

    __shared__ float tot[NACC];
    if (tid < NACC) {
        float s = 0.0f;
        #pragma unroll
        for (int w = 0; w < NTHREADS / 32; w++) s += red[w][tid];
        tot[tid] = s;
    }
    __syncthreads();

    // ---- finalize: each thread writes one cov[m][n] ----
    {
        const int m  = tid >> 4;
        const int n  = tid & 15;
        const int mm = (m < n) ? m : n;
        const int nn = (m < n) ? n : m;
        const float S  = tot[tri_idx(mm, nn)];
        const float sm = tot[NPAIRS + m];
        const float sn = tot[NPAIRS + n];
        const float inv_T  = 1.0f / (float)T_DIM;
        const float inv_T1 = 1.0f / (float)(T_DIM - 1);
        out[(size_t)bc * 256 + tid] = (S - sm * sn * inv_T) * inv_T1;
    }
}

extern "C" void kernel_launch(void* const* d_in, const int* in_sizes, int n_in,
                              void* d_out, int out_size)
{
    const float* x = (const float*)d_in[0];
    float* out = (float*)d_out;
    cov_kernel<<<256, NTHREADS>>>(x, out);
}

// round 4
// speedup vs baseline: 6.6619x; 2.1014x over previous
#include <cuda_runtime.h>

// CovarianceLayer: x [64, 4, 8192, 16] fp32 -> cov [64, 4, 16, 16] fp32
// One CTA per (b,c), 256 threads, 2 CTAs/SM (all 256 CTAs resident in ONE wave).
// Pair-parity split: threads 0-127 accumulate even-m triangle pairs, threads
// 128-255 odd-m pairs, each over rows (tid&127) of every 128-row tile.
// Accumulators are packed f32x2 (fma.rn.f32x2): 40 ull per thread (80 regs).
// Tiles staged double-buffered in smem as pair-transposed float2 [j][row].

#define T_DIM    8192
#define M_DIM    16
#define NTHREADS 256
#define ROWS     128                       // rows per tile
#define NTILES   (T_DIM / ROWS)            // 64
#define PITCH    129                       // float2 (8B) units per pair-column
#define NU       40                        // f32x2 units per half (36 tri + 4 sum)

typedef unsigned long long ull;

__device__ __forceinline__ void fma2(ull& d, ull a, ull b) {
    asm("fma.rn.f32x2 %0, %1, %2, %0;" : "+l"(d) : "l"(a), "l"(b));
}
__device__ __forceinline__ void add2(ull& d, ull a) {
    asm("add.rn.f32x2 %0, %1, %0;" : "+l"(d) : "l"(a));
}
__device__ __forceinline__ float2 u2f(ull u) {
    float2 f; asm("mov.b64 {%0,%1}, %2;" : "=f"(f.x), "=f"(f.y) : "l"(u)); return f;
}
__device__ __forceinline__ ull f2u(float lo, float hi) {
    ull u; asm("mov.b64 %0, {%1,%2};" : "=l"(u) : "f"(lo), "f"(hi)); return u;
}

// prior f32x2 units for m = 2a+HALF within its half
__host__ __device__ __forceinline__ int unit_base(int a) { return 8 * a - a * (a - 1) / 2; }

template <int HALF>
__device__ __forceinline__ void accum_row(ull acc[NU], const ull* __restrict__ tile, int row)
{
    ull vp[8];
    #pragma unroll
    for (int j = 0; j < 8; j++) vp[j] = tile[j * PITCH + row];   // LDS.64, conflict-free

    #pragma unroll
    for (int a = 0; a < 8; a++) {                // m = 2a + HALF
        float2 c = u2f(vp[a]);                   // v[2a], v[2a+1]
        const float vm = HALF ? c.y : c.x;       // v[m]
        const ull bm = f2u(vm, vm);
        const int base = unit_base(a);
        #pragma unroll
        for (int j = a; j < 8; j++)
            fma2(acc[base + j - a], bm, vp[j]);  // (vm*v[2j], vm*v[2j+1])
    }
    #pragma unroll
    for (int j = 0; j < 4; j++)                  // column sums (half owns 4 pairs)
        add2(acc[36 + j], vp[HALF * 4 + j]);
}

__global__ void __launch_bounds__(NTHREADS, 2)
cov_kernel(const float* __restrict__ x, float* __restrict__ out)
{
    __shared__ ull  tile[2][8 * PITCH];          // 2 x 8.0 KB pair-transposed tiles
    __shared__ float red[8][2 * NU];             // per-warp partials (80 floats)
    __shared__ float tot[4 * NU];                // 160 combined sums

    const int bc   = blockIdx.x;
    const int tid  = threadIdx.x;
    const int row  = tid & (ROWS - 1);
    const int half = tid >> 7;

    // gmem as 16B vectors; tile k occupies [k*512, (k+1)*512) float4s
    const ulonglong2* __restrict__ xp =
        reinterpret_cast<const ulonglong2*>(x + (size_t)bc * T_DIM * M_DIM);

    // staging coords: float4 f -> row f>>2, quarter f&3 -> pairs 2q, 2q+1
    const int sr = tid >> 2;          // row for f = tid  (rows 0..63)
    const int sq = tid & 3;

    ull acc[NU];
    #pragma unroll
    for (int i = 0; i < NU; i++) acc[i] = 0ULL;

    ulonglong2 pfa, pfb;

    // ---- prologue: tile 0 load+stage, tile 1 prefetch ----
    pfa = xp[tid];
    pfb = xp[tid + 256];
    tile[0][(2 * sq + 0) * PITCH + sr]      = pfa.x;
    tile[0][(2 * sq + 1) * PITCH + sr]      = pfa.y;
    tile[0][(2 * sq + 0) * PITCH + sr + 64] = pfb.x;
    tile[0][(2 * sq + 1) * PITCH + sr + 64] = pfb.y;
    pfa = xp[512 + tid];
    pfb = xp[512 + tid + 256];
    __syncthreads();

    int cur = 0;
    #pragma unroll 1
    for (int k = 0; k < NTILES; k++) {
        if (k + 1 < NTILES) {                     // stage tile k+1
            tile[cur ^ 1][(2 * sq + 0) * PITCH + sr]      = pfa.x;
            tile[cur ^ 1][(2 * sq + 1) * PITCH + sr]      = pfa.y;
            tile[cur ^ 1][(2 * sq + 0) * PITCH + sr + 64] = pfb.x;
            tile[cur ^ 1][(2 * sq + 1) * PITCH + sr + 64] = pfb.y;
        }
        if (k + 2 < NTILES) {                     // prefetch tile k+2
            pfa = xp[(size_t)(k + 2) * 512 + tid];
            pfb = xp[(size_t)(k + 2) * 512 + tid + 256];
        }

        if (half == 0) accum_row<0>(acc, tile[cur], row);
        else           accum_row<1>(acc, tile[cur], row);

        __syncthreads();
        cur ^= 1;
    }

    // ---- reduce: warp shfl (rows within warp share a half) ----
    const int wid = tid >> 5;
    const int lid = tid & 31;
    #pragma unroll 1
    for (int i = 0; i < NU; i++) {
        float2 f = u2f(acc[i]);
        #pragma unroll
        for (int o = 16; o > 0; o >>= 1) {
            f.x += __shfl_xor_sync(0xFFFFFFFFu, f.x, o);
            f.y += __shfl_xor_sync(0xFFFFFFFFu, f.y, o);
        }
        if (lid == 0) { red[wid][2 * i] = f.x; red[wid][2 * i + 1] = f.y; }
    }
    __syncthreads();

    // combine 4 warps per half: tot[0..79] = half0, tot[80..159] = half1
    if (tid < 4 * NU) {
        const int h = (tid >= 2 * NU);
        const int u = tid - h * 2 * NU;
        float s = 0.0f;
        #pragma unroll
        for (int w = 0; w < 4; w++) s += red[h * 4 + w][u];
        tot[tid] = s;
    }
    __syncthreads();

    // ---- finalize: thread (m,n) ----
    {
        const int m  = tid >> 4;
        const int n  = tid & 15;
        const int mm = (m < n) ? m : n;
        const int nn = (m < n) ? n : m;
        const int H  = mm & 1;
        const int a  = mm >> 1;
        const int j  = nn >> 1;
        const float S = tot[H * 80 + (unit_base(a) + j - a) * 2 + (nn & 1)];

        const int jm = m >> 1, jn = n >> 1;
        const float sm = tot[((jm >= 4) ? 80 : 0) + (36 + (jm & 3)) * 2 + (m & 1)];
        const float sn = tot[((jn >= 4) ? 80 : 0) + (36 + (jn & 3)) * 2 + (n & 1)];

        const float inv_T  = 1.0f / (float)T_DIM;
        const float inv_T1 = 1.0f / (float)(T_DIM - 1);
        out[(size_t)bc * 256 + tid] = (S - sm * sn * inv_T) * inv_T1;
    }
}

extern "C" void kernel_launch(void* const* d_in, const int* in_sizes, int n_in,
                              void* d_out, int out_size)
{
    const float* x = (const float*)d_in[0];
    float* out = (float*)d_out;
    cov_kernel<<<256, NTHREADS>>>(x, out);
}